// round 8
// baseline (speedup 1.0000x reference)
#include <cuda_runtime.h>
#include <cuda_bf16.h>
#include <cstdint>
#include <math.h>

// GMM log-likelihood, Ampere-style mma pipeline (sm_100-safe: no tcgen05).
// lp[b,k] = const_k - 0.5 * || L_k x_b - c_k ||^2 ; out[b] = logsumexp_k lp[b,k]
// Y = X @ L_k^T via bf16 3-term split: Xhi*Lhi + Xlo*Lhi + Xhi*Llo (fp32 accum).
// R7: 512-thread CTA (16 warps, 4/SMSP, occ 25%): warp-level N-split
// (warp w: m-rows (w&7)*16, n-half w>>3). AH register-resident, AL streamed.
// Cross-warp-pair partial ||y||^2 exchange through smem, folded into the
// existing per-component barrier. Grid stays 1024 (comp-split 2).

#define BATCH   65536
#define DIMS    128
#define NCOMP   16
#define MTILE   128
#define NTILES  (BATCH / MTILE)     // 512
#define NBLK    (NTILES * 2)        // 1024
#define KHALF   (NCOMP / 2)         // 8
#define THREADS 512

#define LOG2PI_TERM (-117.6241322501981f)   // -0.5 * 128 * log(2*pi)

// ------------------------- device scratch -------------------------
__device__ __nv_bfloat16 g_Xhi[BATCH * DIMS];
__device__ __nv_bfloat16 g_Xlo[BATCH * DIMS];
__device__ __nv_bfloat16 g_Lhi[NCOMP * DIMS * DIMS];
__device__ __nv_bfloat16 g_Llo[NCOMP * DIMS * DIMS];
__device__ float         g_c[NCOMP * DIMS];
__device__ float         g_kc[NCOMP];
__device__ float         g_pm[2 * BATCH];   // partial running max
__device__ float         g_ps[2 * BATCH];   // partial running sum

// ------------------------- helpers -------------------------
__device__ __forceinline__ uint32_t smem_u32(const void* p) {
    uint32_t a;
    asm("{ .reg .u64 t; cvta.to.shared.u64 t, %1; cvt.u32.u64 %0, t; }"
        : "=r"(a) : "l"(p));
    return a;
}

// XOR swizzle: tile stored [128 rows][128 bf16], 256B/row, 16B chunks.
__device__ __forceinline__ uint32_t swz(int row, int c16) {
    int c = (c16 & 8) | ((c16 ^ row) & 7);
    return (uint32_t)(row * 256 + c * 16);
}

#define CP_COMMIT() asm volatile("cp.async.commit_group;" ::: "memory")

__device__ __forceinline__ void cp16(uint32_t dst, const void* src) {
    asm volatile("cp.async.cg.shared.global [%0], [%1], 16;"
                 :: "r"(dst), "l"(src) : "memory");
}

__device__ __forceinline__ void ldsm_x4(uint32_t* r, uint32_t addr) {
    asm volatile("ldmatrix.sync.aligned.m8n8.x4.shared.b16 {%0,%1,%2,%3}, [%4];"
                 : "=r"(r[0]), "=r"(r[1]), "=r"(r[2]), "=r"(r[3]) : "r"(addr));
}

#define MMA(c, a, b0_, b1_) \
    asm volatile("mma.sync.aligned.m16n8k16.row.col.f32.bf16.bf16.f32 " \
        "{%0,%1,%2,%3}, {%4,%5,%6,%7}, {%8,%9}, {%0,%1,%2,%3};" \
        : "+f"((c)[0]), "+f"((c)[1]), "+f"((c)[2]), "+f"((c)[3]) \
        : "r"((a)[0]), "r"((a)[1]), "r"((a)[2]), "r"((a)[3]), "r"(b0_), "r"(b1_))

// ------------------------- smem layout (dynamic) -------------------------
#define SM_XH  0u
#define SM_XL  32768u
#define SM_LB  65536u       // + buf*65536 ; hi at +0, lo at +32768
#define SM_C   196608u      // 16*128 fp32
#define SM_K   204800u      // 16 fp32 (+pad)
#define SM_P   204864u      // 16 warps x 16 rows fp32 partials = 1KB
#define SMEM_BYTES 205888

// ------------------------- tile loaders (512 threads) -------------------------
__device__ __forceinline__ void load_X_async(uint32_t sb, int m0) {
    const __nv_bfloat16* hi = g_Xhi + (size_t)m0 * DIMS;
    const __nv_bfloat16* lo = g_Xlo + (size_t)m0 * DIMS;
    int t = threadIdx.x;
    #pragma unroll
    for (int i = 0; i < 4; i++) {
        int c = t + i * 512;            // 16B-chunk id 0..2047
        int row = c >> 4, c16 = c & 15;
        uint32_t o = swz(row, c16);
        cp16(sb + SM_XH + o, (const char*)hi + row * 256 + c16 * 16);
        cp16(sb + SM_XL + o, (const char*)lo + row * 256 + c16 * 16);
    }
}

__device__ __forceinline__ void load_L_async(uint32_t sb, int buf, int comp) {
    const __nv_bfloat16* hi = g_Lhi + (size_t)comp * DIMS * DIMS;
    const __nv_bfloat16* lo = g_Llo + (size_t)comp * DIMS * DIMS;
    uint32_t dhi = sb + SM_LB + (uint32_t)buf * 65536u;
    uint32_t dlo = dhi + 32768u;
    int t = threadIdx.x;
    #pragma unroll
    for (int i = 0; i < 4; i++) {
        int c = t + i * 512;
        int row = c >> 4, c16 = c & 15;
        uint32_t o = swz(row, c16);
        cp16(dhi + o, (const char*)hi + row * 256 + c16 * 16);
        cp16(dlo + o, (const char*)lo + row * 256 + c16 * 16);
    }
}

// ------------------------- prep kernels -------------------------
__global__ void split_x_kernel(const float* __restrict__ x) {
    int i = blockIdx.x * blockDim.x + threadIdx.x;
    float v = x[i];
    __nv_bfloat16 h = __float2bfloat16(v);
    g_Xhi[i] = h;
    g_Xlo[i] = __float2bfloat16(v - __bfloat162float(h));
}

__global__ void split_l_kernel(const float* __restrict__ p) {
    int i = blockIdx.x * blockDim.x + threadIdx.x;
    float v = p[i];
    __nv_bfloat16 h = __float2bfloat16(v);
    g_Lhi[i] = h;
    g_Llo[i] = __float2bfloat16(v - __bfloat162float(h));
}

__global__ void prep_c_kernel(const float* __restrict__ p,
                              const float* __restrict__ m,
                              const float* __restrict__ lw) {
    int k = blockIdx.x;
    int i = threadIdx.x;
    const float* L  = p + (size_t)k * DIMS * DIMS + (size_t)i * DIMS;
    const float* mk = m + (size_t)k * DIMS;
    float acc = 0.f;
    #pragma unroll 8
    for (int j = 0; j < DIMS; j++) acc = fmaf(L[j], mk[j], acc);
    g_c[k * DIMS + i] = acc;

    __shared__ float red[DIMS];
    red[i] = logf(L[i]);                    // p[k][i][i]
    __syncthreads();
    for (int st = DIMS / 2; st > 0; st >>= 1) {
        if (i < st) red[i] += red[i + st];
        __syncthreads();
    }
    if (i == 0) g_kc[k] = lw[k] + red[0] + LOG2PI_TERM;
}

// ------------------------- main kernel -------------------------
__global__ void __launch_bounds__(THREADS, 1) gmm_main() {
    extern __shared__ char smem[];
    uint32_t sb = smem_u32(smem);
    int tid   = threadIdx.x;
    int lane  = tid & 31;
    int w     = tid >> 5;           // 0..15
    int wm    = w & 7;              // m-group
    int nhalf = w >> 3;             // n-half (0 or 1)
    int nb    = nhalf * 64;         // n column base
    int tile  = blockIdx.x >> 1;
    int ch    = blockIdx.x & 1;     // component half
    int base  = ch * KHALF;
    int m0    = tile * MTILE;

    float* smC = (float*)(smem + SM_C);
    float* smK = (float*)(smem + SM_K);
    float* smP = (float*)(smem + SM_P);   // [16 warps][16 rows]

    // prologue: X tiles + L[base] (group 0), L[base+1] (group 1)
    load_X_async(sb, m0);
    load_L_async(sb, 0, base);
    CP_COMMIT();
    load_L_async(sb, 1, base + 1);
    CP_COMMIT();

    for (int i = tid; i < NCOMP * DIMS; i += THREADS) smC[i] = g_c[i];
    if (tid < NCOMP) smK[tid] = g_kc[tid];

    asm volatile("cp.async.wait_group 1;" ::: "memory");
    __syncthreads();

    // A hi fragments resident: 8 k16-chunks (this warp's 16 m-rows)
    int arow = wm * 16 + ((lane >> 3) & 1) * 8 + (lane & 7);
    int achi = (lane >> 4) & 1;
    uint32_t AH[8][4];
    #pragma unroll
    for (int kc = 0; kc < 8; kc++)
        ldsm_x4(AH[kc], sb + SM_XH + swz(arow, 2 * kc + achi));

    int g    = lane >> 2;
    int tig  = lane & 3;
    int brow = lane & 7;      // B ldmatrix row within n-tile
    int bci  = lane >> 3;     // B ldmatrix matrix index -> c16 offset

    float rm0 = -INFINITY, rm1 = -INFINITY, rs0 = 0.f, rs1 = 0.f;

    for (int i = 0; i < KHALF; i++) {
        if (i > 0) {
            if (i < KHALF - 1) asm volatile("cp.async.wait_group 1;" ::: "memory");
            else               asm volatile("cp.async.wait_group 0;" ::: "memory");
            __syncthreads();
        }
        int kk = base + i;
        uint32_t Lh = sb + SM_LB + (uint32_t)(i & 1) * 65536u;
        uint32_t Ll = Lh + 32768u;

        float s0 = 0.f, s1 = 0.f;

        // hi-split B fragments double-buffered; prefetch j=0
        uint32_t bh0[2][4], bh1[2][4];
        ldsm_x4(bh0[0], Lh + swz(nb + brow, bci));
        ldsm_x4(bh1[0], Lh + swz(nb + 32 + brow, bci));

        // n-tile pairs (ntp, ntp+4) within this warp's n-half: 4 chains
        #pragma unroll
        for (int ntp = 0; ntp < 4; ntp++) {
            float accA0[4] = {0.f, 0.f, 0.f, 0.f};
            float accB0[4] = {0.f, 0.f, 0.f, 0.f};
            float accA1[4] = {0.f, 0.f, 0.f, 0.f};
            float accB1[4] = {0.f, 0.f, 0.f, 0.f};
            #pragma unroll
            for (int kcp = 0; kcp < 4; kcp++) {
                int j   = ntp * 4 + kcp;
                int cur = j & 1, nxt = cur ^ 1;
                // lo-split B + lo-split A: single-buffered, used >=5 MMAs later
                uint32_t bl0[4], bl1[4], al0[4], al1[4];
                {
                    int r0_ = nb + ntp * 8 + brow;
                    ldsm_x4(bl0, Ll + swz(r0_,      4 * kcp + bci));
                    ldsm_x4(bl1, Ll + swz(r0_ + 32, 4 * kcp + bci));
                    ldsm_x4(al0, sb + SM_XL + swz(arow, 4 * kcp + achi));
                    ldsm_x4(al1, sb + SM_XL + swz(arow, 4 * kcp + 2 + achi));
                }
                // prefetch hi-split B for j+1 (wraps harmlessly at the end)
                {
                    int jn   = j + 1;
                    int ntpn = (jn >> 2) & 3;
                    int kcpn = jn & 3;
                    int rn   = nb + ntpn * 8 + brow;
                    ldsm_x4(bh0[nxt], Lh + swz(rn,      4 * kcpn + bci));
                    ldsm_x4(bh1[nxt], Lh + swz(rn + 32, 4 * kcpn + bci));
                }
                // 12 MMAs, 4 independent chains
                MMA(accA0, AH[2 * kcp],     bh0[cur][0], bh0[cur][1]);
                MMA(accB0, AH[2 * kcp + 1], bh0[cur][2], bh0[cur][3]);
                MMA(accA1, AH[2 * kcp],     bh1[cur][0], bh1[cur][1]);
                MMA(accB1, AH[2 * kcp + 1], bh1[cur][2], bh1[cur][3]);
                MMA(accA0, AH[2 * kcp],     bl0[0], bl0[1]);
                MMA(accB0, AH[2 * kcp + 1], bl0[2], bl0[3]);
                MMA(accA1, AH[2 * kcp],     bl1[0], bl1[1]);
                MMA(accB1, AH[2 * kcp + 1], bl1[2], bl1[3]);
                MMA(accA0, al0, bh0[cur][0], bh0[cur][1]);
                MMA(accB0, al1, bh0[cur][2], bh0[cur][3]);
                MMA(accA1, al0, bh1[cur][0], bh1[cur][1]);
                MMA(accB1, al1, bh1[cur][2], bh1[cur][3]);
            }
            int c0 = kk * DIMS + nb + ntp * 8 + 2 * tig;
            float ca0 = smC[c0];
            float cb0 = smC[c0 + 1];
            float ca1 = smC[c0 + 32];
            float cb1 = smC[c0 + 33];
            float y;
            y = accA0[0] + accB0[0] - ca0; s0 = fmaf(y, y, s0);
            y = accA0[1] + accB0[1] - cb0; s0 = fmaf(y, y, s0);
            y = accA0[2] + accB0[2] - ca0; s1 = fmaf(y, y, s1);
            y = accA0[3] + accB0[3] - cb0; s1 = fmaf(y, y, s1);
            y = accA1[0] + accB1[0] - ca1; s0 = fmaf(y, y, s0);
            y = accA1[1] + accB1[1] - cb1; s0 = fmaf(y, y, s0);
            y = accA1[2] + accB1[2] - ca1; s1 = fmaf(y, y, s1);
            y = accA1[3] + accB1[3] - cb1; s1 = fmaf(y, y, s1);
        }
        // reduce over the 4 threads of each quad (columns)
        s0 += __shfl_xor_sync(0xFFFFFFFFu, s0, 1);
        s0 += __shfl_xor_sync(0xFFFFFFFFu, s0, 2);
        s1 += __shfl_xor_sync(0xFFFFFFFFu, s1, 1);
        s1 += __shfl_xor_sync(0xFFFFFFFFu, s1, 2);

        // cross-warp-pair exchange: warp w and w+8 cover the two n-halves
        if (tig == 0) {
            smP[w * 16 + g]     = s0;
            smP[w * 16 + 8 + g] = s1;
        }
        __syncthreads();

        if (nhalf == 0) {
            float st0 = s0 + smP[(w + 8) * 16 + g];
            float st1 = s1 + smP[(w + 8) * 16 + 8 + g];
            float kc_ = smK[kk];
            float lp0 = kc_ - 0.5f * st0;
            float lp1 = kc_ - 0.5f * st1;
            if (lp0 > rm0) { rs0 = rs0 * __expf(rm0 - lp0) + 1.f; rm0 = lp0; }
            else           { rs0 += __expf(lp0 - rm0); }
            if (lp1 > rm1) { rs1 = rs1 * __expf(rm1 - lp1) + 1.f; rm1 = lp1; }
            else           { rs1 += __expf(lp1 - rm1); }
        }

        if (i + 2 < KHALF) {
            load_L_async(sb, i & 1, base + i + 2);
            CP_COMMIT();
        }
    }

    if (nhalf == 0 && tig == 0) {
        int r0 = m0 + wm * 16 + g;
        g_pm[ch * BATCH + r0]     = rm0;
        g_ps[ch * BATCH + r0]     = rs0;
        g_pm[ch * BATCH + r0 + 8] = rm1;
        g_ps[ch * BATCH + r0 + 8] = rs1;
    }
}

// ------------------------- combine kernel -------------------------
__global__ void combine_kernel(float* __restrict__ out) {
    int b = blockIdx.x * blockDim.x + threadIdx.x;
    float m0 = g_pm[b],         s0 = g_ps[b];
    float m1 = g_pm[BATCH + b], s1 = g_ps[BATCH + b];
    float M  = fmaxf(m0, m1);
    out[b] = M + logf(s0 * __expf(m0 - M) + s1 * __expf(m1 - M));
}

// ------------------------- launch -------------------------
extern "C" void kernel_launch(void* const* d_in, const int* in_sizes, int n_in,
                              void* d_out, int out_size) {
    const float* x     = (const float*)d_in[0];
    const float* means = (const float*)d_in[1];
    const float* prec  = (const float*)d_in[2];
    const float* logw  = (const float*)d_in[3];
    float* out = (float*)d_out;

    cudaFuncSetAttribute(gmm_main,
                         cudaFuncAttributeMaxDynamicSharedMemorySize, SMEM_BYTES);

    split_x_kernel<<<(BATCH * DIMS) / 256, 256>>>(x);
    split_l_kernel<<<(NCOMP * DIMS * DIMS) / 256, 256>>>(prec);
    prep_c_kernel<<<NCOMP, DIMS>>>(prec, means, logw);
    gmm_main<<<NBLK, THREADS, SMEM_BYTES>>>();
    combine_kernel<<<BATCH / 256, 256>>>(out);
}

// round 9
// speedup vs baseline: 1.0002x; 1.0002x over previous
#include <cuda_runtime.h>
#include <cuda_bf16.h>
#include <cstdint>
#include <math.h>

// GMM log-likelihood, Ampere-style mma pipeline (sm_100-safe: no tcgen05).
// lp[b,k] = const_k - 0.5 * || L_k x_b - c_k ||^2 ; out[b] = logsumexp_k lp[b,k]
// Y = X @ L_k^T via bf16 3-term split: Xhi*Lhi + Xlo*Lhi + Xhi*Llo (fp32 accum).
// R8 (on R6 base, 256 thr): ONE barrier per component (load issued after top
// sync, lookahead-1, single cp.async group in flight) and fully deferred
// reduction epilogue (shfl + logsumexp once at the end) so the tensor pipe
// never idles on the shfl/expf chain mid-loop.

#define BATCH   65536
#define DIMS    128
#define NCOMP   16
#define MTILE   128
#define NTILES  (BATCH / MTILE)     // 512
#define NBLK    (NTILES * 2)        // 1024 (2 component-halves per tile)
#define KHALF   (NCOMP / 2)         // 8
#define THREADS 256

#define LOG2PI_TERM (-117.6241322501981f)   // -0.5 * 128 * log(2*pi)

// ------------------------- device scratch -------------------------
__device__ __nv_bfloat16 g_Xhi[BATCH * DIMS];
__device__ __nv_bfloat16 g_Xlo[BATCH * DIMS];
__device__ __nv_bfloat16 g_Lhi[NCOMP * DIMS * DIMS];
__device__ __nv_bfloat16 g_Llo[NCOMP * DIMS * DIMS];
__device__ float         g_c[NCOMP * DIMS];
__device__ float         g_kc[NCOMP];
__device__ float         g_pm[2 * BATCH];   // partial running max
__device__ float         g_ps[2 * BATCH];   // partial running sum

// ------------------------- helpers -------------------------
__device__ __forceinline__ uint32_t smem_u32(const void* p) {
    uint32_t a;
    asm("{ .reg .u64 t; cvta.to.shared.u64 t, %1; cvt.u32.u64 %0, t; }"
        : "=r"(a) : "l"(p));
    return a;
}

// XOR swizzle: tile stored [128 rows][128 bf16], 256B/row, 16B chunks.
__device__ __forceinline__ uint32_t swz(int row, int c16) {
    int c = (c16 & 8) | ((c16 ^ row) & 7);
    return (uint32_t)(row * 256 + c * 16);
}

#define CP_COMMIT() asm volatile("cp.async.commit_group;" ::: "memory")
#define CP_WAIT0()  asm volatile("cp.async.wait_group 0;" ::: "memory")

__device__ __forceinline__ void cp16(uint32_t dst, const void* src) {
    asm volatile("cp.async.cg.shared.global [%0], [%1], 16;"
                 :: "r"(dst), "l"(src) : "memory");
}

__device__ __forceinline__ void ldsm_x4(uint32_t* r, uint32_t addr) {
    asm volatile("ldmatrix.sync.aligned.m8n8.x4.shared.b16 {%0,%1,%2,%3}, [%4];"
                 : "=r"(r[0]), "=r"(r[1]), "=r"(r[2]), "=r"(r[3]) : "r"(addr));
}

#define MMA(c, a, b0_, b1_) \
    asm volatile("mma.sync.aligned.m16n8k16.row.col.f32.bf16.bf16.f32 " \
        "{%0,%1,%2,%3}, {%4,%5,%6,%7}, {%8,%9}, {%0,%1,%2,%3};" \
        : "+f"((c)[0]), "+f"((c)[1]), "+f"((c)[2]), "+f"((c)[3]) \
        : "r"((a)[0]), "r"((a)[1]), "r"((a)[2]), "r"((a)[3]), "r"(b0_), "r"(b1_))

// ------------------------- smem layout (dynamic) -------------------------
#define SM_XH  0u
#define SM_XL  32768u
#define SM_LB  65536u       // + buf*65536 ; hi at +0, lo at +32768
#define SM_C   196608u      // 16*128 fp32
#define SM_K   204800u      // 16 fp32
#define SMEM_BYTES 204928

// ------------------------- tile loaders -------------------------
__device__ __forceinline__ void load_X_async(uint32_t sb, int m0) {
    const __nv_bfloat16* hi = g_Xhi + (size_t)m0 * DIMS;
    const __nv_bfloat16* lo = g_Xlo + (size_t)m0 * DIMS;
    int t = threadIdx.x;
    #pragma unroll
    for (int i = 0; i < 8; i++) {
        int c = t + i * 256;            // 16B-chunk id 0..2047
        int row = c >> 4, c16 = c & 15;
        uint32_t o = swz(row, c16);
        cp16(sb + SM_XH + o, (const char*)hi + row * 256 + c16 * 16);
        cp16(sb + SM_XL + o, (const char*)lo + row * 256 + c16 * 16);
    }
}

__device__ __forceinline__ void load_L_async(uint32_t sb, int buf, int comp) {
    const __nv_bfloat16* hi = g_Lhi + (size_t)comp * DIMS * DIMS;
    const __nv_bfloat16* lo = g_Llo + (size_t)comp * DIMS * DIMS;
    uint32_t dhi = sb + SM_LB + (uint32_t)buf * 65536u;
    uint32_t dlo = dhi + 32768u;
    int t = threadIdx.x;
    #pragma unroll
    for (int i = 0; i < 8; i++) {
        int c = t + i * 256;
        int row = c >> 4, c16 = c & 15;
        uint32_t o = swz(row, c16);
        cp16(dhi + o, (const char*)hi + row * 256 + c16 * 16);
        cp16(dlo + o, (const char*)lo + row * 256 + c16 * 16);
    }
}

// ------------------------- prep kernels -------------------------
__global__ void split_x_kernel(const float* __restrict__ x) {
    int i = blockIdx.x * blockDim.x + threadIdx.x;
    float v = x[i];
    __nv_bfloat16 h = __float2bfloat16(v);
    g_Xhi[i] = h;
    g_Xlo[i] = __float2bfloat16(v - __bfloat162float(h));
}

__global__ void split_l_kernel(const float* __restrict__ p) {
    int i = blockIdx.x * blockDim.x + threadIdx.x;
    float v = p[i];
    __nv_bfloat16 h = __float2bfloat16(v);
    g_Lhi[i] = h;
    g_Llo[i] = __float2bfloat16(v - __bfloat162float(h));
}

__global__ void prep_c_kernel(const float* __restrict__ p,
                              const float* __restrict__ m,
                              const float* __restrict__ lw) {
    int k = blockIdx.x;
    int i = threadIdx.x;
    const float* L  = p + (size_t)k * DIMS * DIMS + (size_t)i * DIMS;
    const float* mk = m + (size_t)k * DIMS;
    float acc = 0.f;
    #pragma unroll 8
    for (int j = 0; j < DIMS; j++) acc = fmaf(L[j], mk[j], acc);
    g_c[k * DIMS + i] = acc;

    __shared__ float red[DIMS];
    red[i] = logf(L[i]);                    // p[k][i][i]
    __syncthreads();
    for (int st = DIMS / 2; st > 0; st >>= 1) {
        if (i < st) red[i] += red[i + st];
        __syncthreads();
    }
    if (i == 0) g_kc[k] = lw[k] + red[0] + LOG2PI_TERM;
}

// ------------------------- main kernel -------------------------
__global__ void __launch_bounds__(THREADS, 1) gmm_main() {
    extern __shared__ char smem[];
    uint32_t sb = smem_u32(smem);
    int tid  = threadIdx.x;
    int lane = tid & 31;
    int w    = tid >> 5;
    int tile = blockIdx.x >> 1;
    int ch   = blockIdx.x & 1;          // component half
    int base = ch * KHALF;
    int m0   = tile * MTILE;

    float* smC = (float*)(smem + SM_C);
    float* smK = (float*)(smem + SM_K);

    // prologue group 0: X tiles + L[base]
    load_X_async(sb, m0);
    load_L_async(sb, 0, base);
    CP_COMMIT();

    for (int i = tid; i < NCOMP * DIMS; i += THREADS) smC[i] = g_c[i];
    if (tid < NCOMP) smK[tid] = g_kc[tid];

    CP_WAIT0();
    __syncthreads();

    // lookahead-1: L[base+1] into buffer 1
    load_L_async(sb, 1, base + 1);
    CP_COMMIT();

    // A fragments (X) resident in registers: 8 k16-chunks x 2 splits
    uint32_t AH[8][4], AL[8][4];
    {
        int arow = w * 16 + ((lane >> 3) & 1) * 8 + (lane & 7);
        int achi = (lane >> 4) & 1;
        #pragma unroll
        for (int kc = 0; kc < 8; kc++) {
            uint32_t o = swz(arow, 2 * kc + achi);
            ldsm_x4(AH[kc], sb + SM_XH + o);
            ldsm_x4(AL[kc], sb + SM_XL + o);
        }
    }

    int g    = lane >> 2;
    int tig  = lane & 3;
    int brow = lane & 7;      // B ldmatrix row within n-tile
    int bci  = lane >> 3;     // B ldmatrix matrix index -> c16 offset

    float sArr0[KHALF], sArr1[KHALF];   // per-component raw partials (deferred)

    for (int i = 0; i < KHALF; i++) {
        if (i > 0) {
            CP_WAIT0();               // load of comp i complete
            __syncthreads();          // all warps done comp i-1 -> buf (i-1)&1 free
            if (i + 1 < KHALF) {
                load_L_async(sb, (i + 1) & 1, base + i + 1);
                CP_COMMIT();
            }
        }
        int kk = base + i;
        uint32_t Lh = sb + SM_LB + (uint32_t)(i & 1) * 65536u;
        uint32_t Ll = Lh + 32768u;

        float s0 = 0.f, s1 = 0.f;

        // hi-split B fragments double-buffered; prefetch j=0
        uint32_t bh0[2][4], bh1[2][4];
        {
            uint32_t oa = swz(brow, bci);
            uint32_t ob = swz(64 + brow, bci);
            ldsm_x4(bh0[0], Lh + oa);
            ldsm_x4(bh1[0], Lh + ob);
        }

        // n-tile pairs (nt, nt+8): 4 independent accumulator chains
        #pragma unroll 2
        for (int nt = 0; nt < 8; nt++) {
            float accA0[4] = {0.f, 0.f, 0.f, 0.f};
            float accB0[4] = {0.f, 0.f, 0.f, 0.f};
            float accA1[4] = {0.f, 0.f, 0.f, 0.f};
            float accB1[4] = {0.f, 0.f, 0.f, 0.f};
            #pragma unroll
            for (int kcp = 0; kcp < 4; kcp++) {
                int j   = nt * 4 + kcp;
                int cur = j & 1, nxt = cur ^ 1;
                // lo-split B fragments: single buffer, used 8 MMAs later
                uint32_t bl0[4], bl1[4];
                {
                    uint32_t oa = swz(nt * 8 + brow,      4 * kcp + bci);
                    uint32_t ob = swz(nt * 8 + 64 + brow, 4 * kcp + bci);
                    ldsm_x4(bl0, Ll + oa);
                    ldsm_x4(bl1, Ll + ob);
                }
                // prefetch hi-split for j+1 (wraps harmlessly at the end)
                {
                    int jn   = j + 1;
                    int ntn  = (jn >> 2) & 7;
                    int kcpn = jn & 3;
                    uint32_t oa = swz(ntn * 8 + brow,      4 * kcpn + bci);
                    uint32_t ob = swz(ntn * 8 + 64 + brow, 4 * kcpn + bci);
                    ldsm_x4(bh0[nxt], Lh + oa);
                    ldsm_x4(bh1[nxt], Lh + ob);
                }
                // 12 MMAs, 4 independent chains, same-chain gap = 4 issues
                MMA(accA0, AH[2 * kcp],     bh0[cur][0], bh0[cur][1]);
                MMA(accB0, AH[2 * kcp + 1], bh0[cur][2], bh0[cur][3]);
                MMA(accA1, AH[2 * kcp],     bh1[cur][0], bh1[cur][1]);
                MMA(accB1, AH[2 * kcp + 1], bh1[cur][2], bh1[cur][3]);
                MMA(accA0, AL[2 * kcp],     bh0[cur][0], bh0[cur][1]);
                MMA(accB0, AL[2 * kcp + 1], bh0[cur][2], bh0[cur][3]);
                MMA(accA1, AL[2 * kcp],     bh1[cur][0], bh1[cur][1]);
                MMA(accB1, AL[2 * kcp + 1], bh1[cur][2], bh1[cur][3]);
                MMA(accA0, AH[2 * kcp],     bl0[0], bl0[1]);
                MMA(accB0, AH[2 * kcp + 1], bl0[2], bl0[3]);
                MMA(accA1, AH[2 * kcp],     bl1[0], bl1[1]);
                MMA(accB1, AH[2 * kcp + 1], bl1[2], bl1[3]);
            }
            float ca0 = smC[kk * DIMS + nt * 8 + 2 * tig];
            float cb0 = smC[kk * DIMS + nt * 8 + 2 * tig + 1];
            float ca1 = smC[kk * DIMS + nt * 8 + 64 + 2 * tig];
            float cb1 = smC[kk * DIMS + nt * 8 + 64 + 2 * tig + 1];
            float y;
            y = accA0[0] + accB0[0] - ca0; s0 = fmaf(y, y, s0);
            y = accA0[1] + accB0[1] - cb0; s0 = fmaf(y, y, s0);
            y = accA0[2] + accB0[2] - ca0; s1 = fmaf(y, y, s1);
            y = accA0[3] + accB0[3] - cb0; s1 = fmaf(y, y, s1);
            y = accA1[0] + accB1[0] - ca1; s0 = fmaf(y, y, s0);
            y = accA1[1] + accB1[1] - cb1; s0 = fmaf(y, y, s0);
            y = accA1[2] + accB1[2] - ca1; s1 = fmaf(y, y, s1);
            y = accA1[3] + accB1[3] - cb1; s1 = fmaf(y, y, s1);
        }
        // stash raw partials; all reduction deferred past the loop
        sArr0[i] = s0;
        sArr1[i] = s1;
    }

    // ---- deferred reduction + logsumexp (no barriers; shfl chains pipeline) ----
    float rm0 = -INFINITY, rm1 = -INFINITY, rs0 = 0.f, rs1 = 0.f;
    #pragma unroll
    for (int i = 0; i < KHALF; i++) {
        float t0 = sArr0[i], t1 = sArr1[i];
        t0 += __shfl_xor_sync(0xFFFFFFFFu, t0, 1);
        t0 += __shfl_xor_sync(0xFFFFFFFFu, t0, 2);
        t1 += __shfl_xor_sync(0xFFFFFFFFu, t1, 1);
        t1 += __shfl_xor_sync(0xFFFFFFFFu, t1, 2);
        float kc_ = smK[base + i];
        float lp0 = kc_ - 0.5f * t0;
        float lp1 = kc_ - 0.5f * t1;
        if (lp0 > rm0) { rs0 = rs0 * __expf(rm0 - lp0) + 1.f; rm0 = lp0; }
        else           { rs0 += __expf(lp0 - rm0); }
        if (lp1 > rm1) { rs1 = rs1 * __expf(rm1 - lp1) + 1.f; rm1 = lp1; }
        else           { rs1 += __expf(lp1 - rm1); }
    }

    if (tig == 0) {
        int r0 = m0 + w * 16 + g;
        g_pm[ch * BATCH + r0]     = rm0;
        g_ps[ch * BATCH + r0]     = rs0;
        g_pm[ch * BATCH + r0 + 8] = rm1;
        g_ps[ch * BATCH + r0 + 8] = rs1;
    }
}

// ------------------------- combine kernel -------------------------
__global__ void combine_kernel(float* __restrict__ out) {
    int b = blockIdx.x * blockDim.x + threadIdx.x;
    float m0 = g_pm[b],         s0 = g_ps[b];
    float m1 = g_pm[BATCH + b], s1 = g_ps[BATCH + b];
    float M  = fmaxf(m0, m1);
    out[b] = M + logf(s0 * __expf(m0 - M) + s1 * __expf(m1 - M));
}

// ------------------------- launch -------------------------
extern "C" void kernel_launch(void* const* d_in, const int* in_sizes, int n_in,
                              void* d_out, int out_size) {
    const float* x     = (const float*)d_in[0];
    const float* means = (const float*)d_in[1];
    const float* prec  = (const float*)d_in[2];
    const float* logw  = (const float*)d_in[3];
    float* out = (float*)d_out;

    cudaFuncSetAttribute(gmm_main,
                         cudaFuncAttributeMaxDynamicSharedMemorySize, SMEM_BYTES);

    split_x_kernel<<<(BATCH * DIMS) / 256, 256>>>(x);
    split_l_kernel<<<(NCOMP * DIMS * DIMS) / 256, 256>>>(prec);
    prep_c_kernel<<<NCOMP, DIMS>>>(prec, means, logw);
    gmm_main<<<NBLK, THREADS, SMEM_BYTES>>>();
    combine_kernel<<<BATCH / 256, 256>>>(out);
}

// round 10
// speedup vs baseline: 2.1371x; 2.1367x over previous
#include <cuda_runtime.h>
#include <cuda_fp16.h>
#include <cstdint>
#include <math.h>

// GMM log-likelihood, single-pass fp16 HMMA (sm_100-safe: no tcgen05).
// lp[b,k] = const_k - 0.5 * || Lh_k xh_b - c_k ||^2 ; out[b] = logsumexp_k lp
//   c_k = Lh_k m_k (fp32, rounded-L consistent), const_k uses EXACT diag logdet.
// R9: fp16 1-pass (error ~3e-5 << 1e-3), smem 104KB -> 2 CTAs/SM, 3x fewer MMAs.

#define BATCH   65536
#define DIMS    128
#define NCOMP   16
#define MTILE   128
#define NTILES  (BATCH / MTILE)     // 512
#define NBLK    (NTILES * 2)        // 1024 (2 component-halves per tile)
#define KHALF   (NCOMP / 2)         // 8
#define THREADS 256

#define LOG2PI_TERM (-117.6241322501981f)   // -0.5 * 128 * log(2*pi)

// ------------------------- device scratch -------------------------
__device__ __half g_Xh[BATCH * DIMS];
__device__ __half g_Lh[NCOMP * DIMS * DIMS];
__device__ float  g_c[NCOMP * DIMS];
__device__ float  g_kc[NCOMP];
__device__ float  g_pm[2 * BATCH];   // partial running max
__device__ float  g_ps[2 * BATCH];   // partial running sum

// ------------------------- helpers -------------------------
__device__ __forceinline__ uint32_t smem_u32(const void* p) {
    uint32_t a;
    asm("{ .reg .u64 t; cvta.to.shared.u64 t, %1; cvt.u32.u64 %0, t; }"
        : "=r"(a) : "l"(p));
    return a;
}

// XOR swizzle: tile stored [128 rows][128 fp16], 256B/row, 16B chunks.
__device__ __forceinline__ uint32_t swz(int row, int c16) {
    int c = (c16 & 8) | ((c16 ^ row) & 7);
    return (uint32_t)(row * 256 + c * 16);
}

#define CP_COMMIT() asm volatile("cp.async.commit_group;" ::: "memory")
#define CP_WAIT0()  asm volatile("cp.async.wait_group 0;" ::: "memory")
#define CP_WAIT1()  asm volatile("cp.async.wait_group 1;" ::: "memory")

__device__ __forceinline__ void cp16(uint32_t dst, const void* src) {
    asm volatile("cp.async.cg.shared.global [%0], [%1], 16;"
                 :: "r"(dst), "l"(src) : "memory");
}

__device__ __forceinline__ void ldsm_x4(uint32_t* r, uint32_t addr) {
    asm volatile("ldmatrix.sync.aligned.m8n8.x4.shared.b16 {%0,%1,%2,%3}, [%4];"
                 : "=r"(r[0]), "=r"(r[1]), "=r"(r[2]), "=r"(r[3]) : "r"(addr));
}

#define MMA(c, a, b0_, b1_) \
    asm volatile("mma.sync.aligned.m16n8k16.row.col.f32.f16.f16.f32 " \
        "{%0,%1,%2,%3}, {%4,%5,%6,%7}, {%8,%9}, {%0,%1,%2,%3};" \
        : "+f"((c)[0]), "+f"((c)[1]), "+f"((c)[2]), "+f"((c)[3]) \
        : "r"((a)[0]), "r"((a)[1]), "r"((a)[2]), "r"((a)[3]), "r"(b0_), "r"(b1_))

// ------------------------- smem layout (dynamic) -------------------------
#define SM_XH  0u           // 32 KB
#define SM_LB  32768u       // + buf*32768, 2 buffers (32 KB each)
#define SM_C   98304u       // 16*128 fp32 = 8 KB
#define SM_K   106496u      // 16 fp32
#define SMEM_BYTES 106560

// ------------------------- tile loaders -------------------------
__device__ __forceinline__ void load_X_async(uint32_t sb, int m0) {
    const __half* src = g_Xh + (size_t)m0 * DIMS;
    int t = threadIdx.x;
    #pragma unroll
    for (int i = 0; i < 8; i++) {
        int c = t + i * 256;            // 16B-chunk id 0..2047
        int row = c >> 4, c16 = c & 15;
        cp16(sb + SM_XH + swz(row, c16), (const char*)src + row * 256 + c16 * 16);
    }
}

__device__ __forceinline__ void load_L_async(uint32_t sb, int buf, int comp) {
    const __half* src = g_Lh + (size_t)comp * DIMS * DIMS;
    uint32_t dst = sb + SM_LB + (uint32_t)buf * 32768u;
    int t = threadIdx.x;
    #pragma unroll
    for (int i = 0; i < 8; i++) {
        int c = t + i * 256;
        int row = c >> 4, c16 = c & 15;
        cp16(dst + swz(row, c16), (const char*)src + row * 256 + c16 * 16);
    }
}

// ------------------------- prep kernels -------------------------
__global__ void cvt_x_kernel(const float* __restrict__ x) {
    int i = blockIdx.x * blockDim.x + threadIdx.x;
    g_Xh[i] = __float2half(x[i]);
}

__global__ void cvt_l_kernel(const float* __restrict__ p) {
    int i = blockIdx.x * blockDim.x + threadIdx.x;
    g_Lh[i] = __float2half(p[i]);
}

__global__ void prep_c_kernel(const float* __restrict__ p,
                              const float* __restrict__ m,
                              const float* __restrict__ lw) {
    int k = blockIdx.x;
    int i = threadIdx.x;
    const float* L  = p + (size_t)k * DIMS * DIMS + (size_t)i * DIMS;
    const float* mk = m + (size_t)k * DIMS;
    // c uses the fp16-ROUNDED L so the GEMM error correlates as (Lh-L)(x-m)
    float acc = 0.f;
    #pragma unroll 8
    for (int j = 0; j < DIMS; j++)
        acc = fmaf(__half2float(__float2half(L[j])), mk[j], acc);
    g_c[k * DIMS + i] = acc;

    __shared__ float red[DIMS];
    red[i] = logf(L[i]);                    // EXACT diag p[k][i][i]
    __syncthreads();
    for (int st = DIMS / 2; st > 0; st >>= 1) {
        if (i < st) red[i] += red[i + st];
        __syncthreads();
    }
    if (i == 0) g_kc[k] = lw[k] + red[0] + LOG2PI_TERM;
}

// ------------------------- main kernel -------------------------
__global__ void __launch_bounds__(THREADS, 2) gmm_main() {
    extern __shared__ char smem[];
    uint32_t sb = smem_u32(smem);
    int tid  = threadIdx.x;
    int lane = tid & 31;
    int w    = tid >> 5;
    int tile = blockIdx.x >> 1;
    int ch   = blockIdx.x & 1;          // component half
    int base = ch * KHALF;
    int m0   = tile * MTILE;

    float* smC = (float*)(smem + SM_C);
    float* smK = (float*)(smem + SM_K);

    // prologue: group(X + L[base]) then group(L[base+1])
    load_X_async(sb, m0);
    load_L_async(sb, 0, base);
    CP_COMMIT();
    load_L_async(sb, 1, base + 1);
    CP_COMMIT();

    for (int i = tid; i < NCOMP * DIMS; i += THREADS) smC[i] = g_c[i];
    if (tid < NCOMP) smK[tid] = g_kc[tid];

    CP_WAIT1();
    __syncthreads();

    // A fragments (Xh) resident: 8 k16-chunks
    uint32_t AH[8][4];
    {
        int arow = w * 16 + ((lane >> 3) & 1) * 8 + (lane & 7);
        int achi = (lane >> 4) & 1;
        #pragma unroll
        for (int kc = 0; kc < 8; kc++)
            ldsm_x4(AH[kc], sb + SM_XH + swz(arow, 2 * kc + achi));
    }

    int g    = lane >> 2;
    int tig  = lane & 3;
    int brow = lane & 7;      // B ldmatrix row within n-tile
    int bci  = lane >> 3;     // B ldmatrix matrix index -> c16 offset

    float rm0 = -INFINITY, rm1 = -INFINITY, rs0 = 0.f, rs1 = 0.f;

    for (int i = 0; i < KHALF; i++) {
        if (i > 0) {
            CP_WAIT0();               // L[base+i] resident
            __syncthreads();          // all warps done comp i-1 -> its buffer free
            if (i + 1 < KHALF) {
                load_L_async(sb, (i + 1) & 1, base + i + 1);
                CP_COMMIT();
            }
        }
        int kk = base + i;
        uint32_t Lh = sb + SM_LB + (uint32_t)(i & 1) * 32768u;

        float s0 = 0.f, s1 = 0.f;

        // B fragments double-buffered; prefetch j=0
        uint32_t bh0[2][4], bh1[2][4];
        ldsm_x4(bh0[0], Lh + swz(brow, bci));
        ldsm_x4(bh1[0], Lh + swz(64 + brow, bci));

        // n-tile pairs (nt, nt+8): 4 independent accumulator chains
        #pragma unroll 2
        for (int nt = 0; nt < 8; nt++) {
            float accA0[4] = {0.f, 0.f, 0.f, 0.f};
            float accB0[4] = {0.f, 0.f, 0.f, 0.f};
            float accA1[4] = {0.f, 0.f, 0.f, 0.f};
            float accB1[4] = {0.f, 0.f, 0.f, 0.f};
            #pragma unroll
            for (int kcp = 0; kcp < 4; kcp++) {
                int j   = nt * 4 + kcp;
                int cur = j & 1, nxt = cur ^ 1;
                // prefetch B for j+1 (wraps harmlessly to (0,0) at the end)
                {
                    int jn   = j + 1;
                    int ntn  = (jn >> 2) & 7;
                    int kcpn = jn & 3;
                    ldsm_x4(bh0[nxt], Lh + swz(ntn * 8 + brow,      4 * kcpn + bci));
                    ldsm_x4(bh1[nxt], Lh + swz(ntn * 8 + 64 + brow, 4 * kcpn + bci));
                }
                // 4 MMAs, 4 independent chains
                MMA(accA0, AH[2 * kcp],     bh0[cur][0], bh0[cur][1]);
                MMA(accB0, AH[2 * kcp + 1], bh0[cur][2], bh0[cur][3]);
                MMA(accA1, AH[2 * kcp],     bh1[cur][0], bh1[cur][1]);
                MMA(accB1, AH[2 * kcp + 1], bh1[cur][2], bh1[cur][3]);
            }
            float ca0 = smC[kk * DIMS + nt * 8 + 2 * tig];
            float cb0 = smC[kk * DIMS + nt * 8 + 2 * tig + 1];
            float ca1 = smC[kk * DIMS + nt * 8 + 64 + 2 * tig];
            float cb1 = smC[kk * DIMS + nt * 8 + 64 + 2 * tig + 1];
            float y;
            y = accA0[0] + accB0[0] - ca0; s0 = fmaf(y, y, s0);
            y = accA0[1] + accB0[1] - cb0; s0 = fmaf(y, y, s0);
            y = accA0[2] + accB0[2] - ca0; s1 = fmaf(y, y, s1);
            y = accA0[3] + accB0[3] - cb0; s1 = fmaf(y, y, s1);
            y = accA1[0] + accB1[0] - ca1; s0 = fmaf(y, y, s0);
            y = accA1[1] + accB1[1] - cb1; s0 = fmaf(y, y, s0);
            y = accA1[2] + accB1[2] - ca1; s1 = fmaf(y, y, s1);
            y = accA1[3] + accB1[3] - cb1; s1 = fmaf(y, y, s1);
        }
        // reduce over the 4 threads of each quad (columns)
        s0 += __shfl_xor_sync(0xFFFFFFFFu, s0, 1);
        s0 += __shfl_xor_sync(0xFFFFFFFFu, s0, 2);
        s1 += __shfl_xor_sync(0xFFFFFFFFu, s1, 1);
        s1 += __shfl_xor_sync(0xFFFFFFFFu, s1, 2);

        float kc_ = smK[kk];
        float lp0 = kc_ - 0.5f * s0;
        float lp1 = kc_ - 0.5f * s1;
        if (lp0 > rm0) { rs0 = rs0 * __expf(rm0 - lp0) + 1.f; rm0 = lp0; }
        else           { rs0 += __expf(lp0 - rm0); }
        if (lp1 > rm1) { rs1 = rs1 * __expf(rm1 - lp1) + 1.f; rm1 = lp1; }
        else           { rs1 += __expf(lp1 - rm1); }
    }

    if (tig == 0) {
        int r0 = m0 + w * 16 + g;
        g_pm[ch * BATCH + r0]     = rm0;
        g_ps[ch * BATCH + r0]     = rs0;
        g_pm[ch * BATCH + r0 + 8] = rm1;
        g_ps[ch * BATCH + r0 + 8] = rs1;
    }
}

// ------------------------- combine kernel -------------------------
__global__ void combine_kernel(float* __restrict__ out) {
    int b = blockIdx.x * blockDim.x + threadIdx.x;
    float m0 = g_pm[b],         s0 = g_ps[b];
    float m1 = g_pm[BATCH + b], s1 = g_ps[BATCH + b];
    float M  = fmaxf(m0, m1);
    out[b] = M + logf(s0 * __expf(m0 - M) + s1 * __expf(m1 - M));
}

// ------------------------- launch -------------------------
extern "C" void kernel_launch(void* const* d_in, const int* in_sizes, int n_in,
                              void* d_out, int out_size) {
    const float* x     = (const float*)d_in[0];
    const float* means = (const float*)d_in[1];
    const float* prec  = (const float*)d_in[2];
    const float* logw  = (const float*)d_in[3];
    float* out = (float*)d_out;

    cudaFuncSetAttribute(gmm_main,
                         cudaFuncAttributeMaxDynamicSharedMemorySize, SMEM_BYTES);

    cvt_x_kernel<<<(BATCH * DIMS) / 256, 256>>>(x);
    cvt_l_kernel<<<(NCOMP * DIMS * DIMS) / 256, 256>>>(prec);
    prep_c_kernel<<<NCOMP, DIMS>>>(prec, means, logw);
    gmm_main<<<NBLK, THREADS, SMEM_BYTES>>>();
    combine_kernel<<<BATCH / 256, 256>>>(out);
}